// round 1
// baseline (speedup 1.0000x reference)
#include <cuda_runtime.h>

// Problem constants (fixed by setup_inputs)
#define Bb   8
#define Nn   4096
#define Ee   16384
#define Pp   64
#define Dd   256
#define Hh   512
#define MSGm 256
#define UPDu 254
#define STEPS 3

// Scratch (device globals per harness allocation rules)
__device__ __align__(128) float g_ns [(size_t)Bb * Nn * Dd];   //  33.5 MB, mutable node states
__device__ __align__(128) float g_h  [(size_t)Bb * Ee * Hh];   // 268   MB, edge hidden
__device__ __align__(128) float g_inc[(size_t)Bb * Nn * MSGm]; //  33.5 MB, scattered messages
__device__ __align__(128) float g_h2 [(size_t)Bb * Nn * Hh];   //  67   MB, node hidden

// ---------------------------------------------------------------------------
__global__ void k_copy_ns(const float* __restrict__ src) {
    size_t i = (size_t)blockIdx.x * blockDim.x + threadIdx.x;
    if (i < ((size_t)Bb * Nn * Dd) / 4) {
        ((float4*)g_ns)[i] = ((const float4*)src)[i];
    }
}

__global__ void k_zero_inc() {
    size_t i = (size_t)blockIdx.x * blockDim.x + threadIdx.x;
    if (i < ((size_t)Bb * Nn * MSGm) / 4) {
        ((float4*)g_inc)[i] = make_float4(0.f, 0.f, 0.f, 0.f);
    }
}

// ---------------------------------------------------------------------------
// Edge MLP layer 1:
// g_h[row, :] = relu( concat(ns[b,src[e]], ns[b,snk[e]]) @ W_e1 + b_e1 )
// row = b*E + e ;  M = 131072, N = 512, K = 512.  Tile 128x128x8, 256 thr.
__global__ __launch_bounds__(256)
void k_edge1(const float* __restrict__ We1, const float* __restrict__ be1,
             const int* __restrict__ esrc, const int* __restrict__ esnk)
{
    __shared__ float As[8][128];
    __shared__ float Bs[8][128];
    __shared__ int   sIdx[2][128];

    const int tid = threadIdx.x;
    const int tx  = tid & 15;
    const int ty  = tid >> 4;
    const int rowBase = blockIdx.y * 128;   // within [0, B*E)
    const int colBase = blockIdx.x * 128;
    const int b  = rowBase >> 14;           // E = 16384
    const int e0 = rowBase & (Ee - 1);

    if (tid < 128)       sIdx[0][tid]       = esrc[e0 + tid];
    else                 sIdx[1][tid - 128] = esnk[e0 + tid - 128];
    __syncthreads();

    const float* nsb = g_ns + (size_t)b * Nn * Dd;

    const int ar  = tid >> 1;          // 0..127 : A row in tile
    const int akq = (tid & 1) * 4;     // 0 or 4 : k offset
    const int bk  = tid >> 5;          // 0..7   : B k row
    const int bc  = (tid & 31) * 4;    // 0..124 : B col

    float acc[8][8];
#pragma unroll
    for (int i = 0; i < 8; i++)
#pragma unroll
        for (int j = 0; j < 8; j++) acc[i][j] = 0.f;

    for (int k0 = 0; k0 < 2 * Dd; k0 += 8) {
        int kg   = k0 + akq;
        int half = kg >> 8;
        int idx  = sIdx[half][ar];
        float4 a4 = *(const float4*)(nsb + (size_t)idx * Dd + (kg & (Dd - 1)));
        As[akq + 0][ar] = a4.x; As[akq + 1][ar] = a4.y;
        As[akq + 2][ar] = a4.z; As[akq + 3][ar] = a4.w;
        float4 b4 = *(const float4*)(We1 + (size_t)(k0 + bk) * Hh + colBase + bc);
        *(float4*)&Bs[bk][bc] = b4;
        __syncthreads();
#pragma unroll
        for (int kk = 0; kk < 8; kk++) {
            float4 a0 = *(const float4*)&As[kk][ty * 4];
            float4 a1 = *(const float4*)&As[kk][ty * 4 + 64];
            float4 b0 = *(const float4*)&Bs[kk][tx * 4];
            float4 b1 = *(const float4*)&Bs[kk][tx * 4 + 64];
            float a[8] = {a0.x, a0.y, a0.z, a0.w, a1.x, a1.y, a1.z, a1.w};
            float bb[8] = {b0.x, b0.y, b0.z, b0.w, b1.x, b1.y, b1.z, b1.w};
#pragma unroll
            for (int i = 0; i < 8; i++)
#pragma unroll
                for (int j = 0; j < 8; j++)
                    acc[i][j] = fmaf(a[i], bb[j], acc[i][j]);
        }
        __syncthreads();
    }

    float bias[8];
#pragma unroll
    for (int j = 0; j < 8; j++)
        bias[j] = be1[colBase + tx * 4 + (j & 3) + (j >> 2) * 64];
#pragma unroll
    for (int i = 0; i < 8; i++) {
        int row = rowBase + ty * 4 + (i & 3) + (i >> 2) * 64;
        float* outp = g_h + (size_t)row * Hh + colBase;
        float4 v0, v1;
        v0.x = fmaxf(acc[i][0] + bias[0], 0.f);
        v0.y = fmaxf(acc[i][1] + bias[1], 0.f);
        v0.z = fmaxf(acc[i][2] + bias[2], 0.f);
        v0.w = fmaxf(acc[i][3] + bias[3], 0.f);
        v1.x = fmaxf(acc[i][4] + bias[4], 0.f);
        v1.y = fmaxf(acc[i][5] + bias[5], 0.f);
        v1.z = fmaxf(acc[i][6] + bias[6], 0.f);
        v1.w = fmaxf(acc[i][7] + bias[7], 0.f);
        *(float4*)(outp + tx * 4)      = v0;
        *(float4*)(outp + tx * 4 + 64) = v1;
    }
}

// ---------------------------------------------------------------------------
// Edge MLP layer 2 + scatter:
// msgs = g_h @ W_e2 + b_e2 ; atomicAdd into g_inc[b, snk[e], :]
// M = 131072, N = 256, K = 512.
__global__ __launch_bounds__(256)
void k_edge2(const float* __restrict__ We2, const float* __restrict__ be2,
             const int* __restrict__ esnk)
{
    __shared__ float As[8][128];
    __shared__ float Bs[8][128];
    __shared__ int   sSnk[128];

    const int tid = threadIdx.x;
    const int tx  = tid & 15;
    const int ty  = tid >> 4;
    const int rowBase = blockIdx.y * 128;
    const int colBase = blockIdx.x * 128;
    const int b  = rowBase >> 14;
    const int e0 = rowBase & (Ee - 1);

    if (tid < 128) sSnk[tid] = esnk[e0 + tid];
    __syncthreads();

    const float* A = g_h + (size_t)rowBase * Hh;

    const int ar  = tid >> 1;
    const int akq = (tid & 1) * 4;
    const int bk  = tid >> 5;
    const int bc  = (tid & 31) * 4;

    float acc[8][8];
#pragma unroll
    for (int i = 0; i < 8; i++)
#pragma unroll
        for (int j = 0; j < 8; j++) acc[i][j] = 0.f;

    for (int k0 = 0; k0 < Hh; k0 += 8) {
        float4 a4 = *(const float4*)(A + (size_t)ar * Hh + k0 + akq);
        As[akq + 0][ar] = a4.x; As[akq + 1][ar] = a4.y;
        As[akq + 2][ar] = a4.z; As[akq + 3][ar] = a4.w;
        float4 b4 = *(const float4*)(We2 + (size_t)(k0 + bk) * MSGm + colBase + bc);
        *(float4*)&Bs[bk][bc] = b4;
        __syncthreads();
#pragma unroll
        for (int kk = 0; kk < 8; kk++) {
            float4 a0 = *(const float4*)&As[kk][ty * 4];
            float4 a1 = *(const float4*)&As[kk][ty * 4 + 64];
            float4 b0 = *(const float4*)&Bs[kk][tx * 4];
            float4 b1 = *(const float4*)&Bs[kk][tx * 4 + 64];
            float a[8] = {a0.x, a0.y, a0.z, a0.w, a1.x, a1.y, a1.z, a1.w};
            float bb[8] = {b0.x, b0.y, b0.z, b0.w, b1.x, b1.y, b1.z, b1.w};
#pragma unroll
            for (int i = 0; i < 8; i++)
#pragma unroll
                for (int j = 0; j < 8; j++)
                    acc[i][j] = fmaf(a[i], bb[j], acc[i][j]);
        }
        __syncthreads();
    }

    float bias[8];
#pragma unroll
    for (int j = 0; j < 8; j++)
        bias[j] = be2[colBase + tx * 4 + (j & 3) + (j >> 2) * 64];
#pragma unroll
    for (int i = 0; i < 8; i++) {
        int r   = ty * 4 + (i & 3) + (i >> 2) * 64;
        int snk = sSnk[r];
        float* dst = g_inc + ((size_t)b * Nn + snk) * MSGm + colBase;
#pragma unroll
        for (int j = 0; j < 8; j++) {
            int c = tx * 4 + (j & 3) + (j >> 2) * 64;
            atomicAdd(dst + c, acc[i][j] + bias[j]);
        }
    }
}

// ---------------------------------------------------------------------------
// Node MLP layer 1:
// g_h2[row,:] = relu( concat(g_inc[row,:], g_ns[row,:]) @ W_n1 + b_n1 )
// M = 32768, N = 512, K = 512.
__global__ __launch_bounds__(256)
void k_node1(const float* __restrict__ Wn1, const float* __restrict__ bn1)
{
    __shared__ float As[8][128];
    __shared__ float Bs[8][128];

    const int tid = threadIdx.x;
    const int tx  = tid & 15;
    const int ty  = tid >> 4;
    const int rowBase = blockIdx.y * 128;   // within [0, B*N)
    const int colBase = blockIdx.x * 128;

    const int ar  = tid >> 1;
    const int akq = (tid & 1) * 4;
    const int bk  = tid >> 5;
    const int bc  = (tid & 31) * 4;

    float acc[8][8];
#pragma unroll
    for (int i = 0; i < 8; i++)
#pragma unroll
        for (int j = 0; j < 8; j++) acc[i][j] = 0.f;

    for (int k0 = 0; k0 < Dd + MSGm; k0 += 8) {
        int kg = k0 + akq;
        const float* src = (kg < MSGm)
            ? (g_inc + (size_t)(rowBase + ar) * MSGm + kg)
            : (g_ns  + (size_t)(rowBase + ar) * Dd  + (kg - MSGm));
        float4 a4 = *(const float4*)src;
        As[akq + 0][ar] = a4.x; As[akq + 1][ar] = a4.y;
        As[akq + 2][ar] = a4.z; As[akq + 3][ar] = a4.w;
        float4 b4 = *(const float4*)(Wn1 + (size_t)(k0 + bk) * Hh + colBase + bc);
        *(float4*)&Bs[bk][bc] = b4;
        __syncthreads();
#pragma unroll
        for (int kk = 0; kk < 8; kk++) {
            float4 a0 = *(const float4*)&As[kk][ty * 4];
            float4 a1 = *(const float4*)&As[kk][ty * 4 + 64];
            float4 b0 = *(const float4*)&Bs[kk][tx * 4];
            float4 b1 = *(const float4*)&Bs[kk][tx * 4 + 64];
            float a[8] = {a0.x, a0.y, a0.z, a0.w, a1.x, a1.y, a1.z, a1.w};
            float bb[8] = {b0.x, b0.y, b0.z, b0.w, b1.x, b1.y, b1.z, b1.w};
#pragma unroll
            for (int i = 0; i < 8; i++)
#pragma unroll
                for (int j = 0; j < 8; j++)
                    acc[i][j] = fmaf(a[i], bb[j], acc[i][j]);
        }
        __syncthreads();
    }

    float bias[8];
#pragma unroll
    for (int j = 0; j < 8; j++)
        bias[j] = bn1[colBase + tx * 4 + (j & 3) + (j >> 2) * 64];
#pragma unroll
    for (int i = 0; i < 8; i++) {
        int row = rowBase + ty * 4 + (i & 3) + (i >> 2) * 64;
        float* outp = g_h2 + (size_t)row * Hh + colBase;
        float4 v0, v1;
        v0.x = fmaxf(acc[i][0] + bias[0], 0.f);
        v0.y = fmaxf(acc[i][1] + bias[1], 0.f);
        v0.z = fmaxf(acc[i][2] + bias[2], 0.f);
        v0.w = fmaxf(acc[i][3] + bias[3], 0.f);
        v1.x = fmaxf(acc[i][4] + bias[4], 0.f);
        v1.y = fmaxf(acc[i][5] + bias[5], 0.f);
        v1.z = fmaxf(acc[i][6] + bias[6], 0.f);
        v1.w = fmaxf(acc[i][7] + bias[7], 0.f);
        *(float4*)(outp + tx * 4)      = v0;
        *(float4*)(outp + tx * 4 + 64) = v1;
    }
}

// ---------------------------------------------------------------------------
// Node MLP layer 2 + in-place state update:
// upd = g_h2 @ W_n2 + b_n2 ; g_ns[row, 2 + c] += upd[row, c]   (c < 254)
// M = 32768, N = 254, K = 512.
__global__ __launch_bounds__(256)
void k_node2(const float* __restrict__ Wn2, const float* __restrict__ bn2)
{
    __shared__ float As[8][128];
    __shared__ float Bs[8][128];

    const int tid = threadIdx.x;
    const int tx  = tid & 15;
    const int ty  = tid >> 4;
    const int rowBase = blockIdx.y * 128;
    const int colBase = blockIdx.x * 128;

    const int ar  = tid >> 1;
    const int akq = (tid & 1) * 4;
    const int bk  = tid >> 5;
    const int bc  = (tid & 31) * 4;

    float acc[8][8];
#pragma unroll
    for (int i = 0; i < 8; i++)
#pragma unroll
        for (int j = 0; j < 8; j++) acc[i][j] = 0.f;

    const float* A = g_h2 + (size_t)rowBase * Hh;

    for (int k0 = 0; k0 < Hh; k0 += 8) {
        float4 a4 = *(const float4*)(A + (size_t)ar * Hh + k0 + akq);
        As[akq + 0][ar] = a4.x; As[akq + 1][ar] = a4.y;
        As[akq + 2][ar] = a4.z; As[akq + 3][ar] = a4.w;
#pragma unroll
        for (int u = 0; u < 4; u++) {
            int c = colBase + bc + u;
            Bs[bk][bc + u] = (c < UPDu) ? Wn2[(size_t)(k0 + bk) * UPDu + c] : 0.f;
        }
        __syncthreads();
#pragma unroll
        for (int kk = 0; kk < 8; kk++) {
            float4 a0 = *(const float4*)&As[kk][ty * 4];
            float4 a1 = *(const float4*)&As[kk][ty * 4 + 64];
            float4 b0 = *(const float4*)&Bs[kk][tx * 4];
            float4 b1 = *(const float4*)&Bs[kk][tx * 4 + 64];
            float a[8] = {a0.x, a0.y, a0.z, a0.w, a1.x, a1.y, a1.z, a1.w};
            float bb[8] = {b0.x, b0.y, b0.z, b0.w, b1.x, b1.y, b1.z, b1.w};
#pragma unroll
            for (int i = 0; i < 8; i++)
#pragma unroll
                for (int j = 0; j < 8; j++)
                    acc[i][j] = fmaf(a[i], bb[j], acc[i][j]);
        }
        __syncthreads();
    }

#pragma unroll
    for (int i = 0; i < 8; i++) {
        int row = rowBase + ty * 4 + (i & 3) + (i >> 2) * 64;
        float* nsrow = g_ns + (size_t)row * Dd;
#pragma unroll
        for (int j = 0; j < 8; j++) {
            int c = colBase + tx * 4 + (j & 3) + (j >> 2) * 64;
            if (c < UPDu) {
                nsrow[2 + c] += acc[i][j] + bn2[c];
            }
        }
    }
}

// ---------------------------------------------------------------------------
// Extraction: out[b,p,d] = sum_n attn[b,p,n] * ns[b,n,d]
__global__ __launch_bounds__(256)
void k_extract(const float* __restrict__ attn, float* __restrict__ out)
{
    const int p = blockIdx.x;
    const int b = blockIdx.y;
    const int d = threadIdx.x;

    const float* ap  = attn + ((size_t)b * Pp + p) * Nn;
    const float* nsb = g_ns + (size_t)b * Nn * Dd;

    __shared__ float sa[256];
    float acc0 = 0.f, acc1 = 0.f;
    for (int n0 = 0; n0 < Nn; n0 += 256) {
        sa[d] = ap[n0 + d];
        __syncthreads();
#pragma unroll 8
        for (int n = 0; n < 256; n += 2) {
            acc0 = fmaf(sa[n],     nsb[(size_t)(n0 + n) * Dd + d],     acc0);
            acc1 = fmaf(sa[n + 1], nsb[(size_t)(n0 + n + 1) * Dd + d], acc1);
        }
        __syncthreads();
    }
    out[((size_t)b * Pp + p) * Dd + d] = acc0 + acc1;
}

// ---------------------------------------------------------------------------
extern "C" void kernel_launch(void* const* d_in, const int* in_sizes, int n_in,
                              void* d_out, int out_size)
{
    const float* nodes = (const float*)d_in[0];
    const float* attn  = (const float*)d_in[1];
    const float* We1   = (const float*)d_in[2];
    const float* be1   = (const float*)d_in[3];
    const float* We2   = (const float*)d_in[4];
    const float* be2   = (const float*)d_in[5];
    const float* Wn1   = (const float*)d_in[6];
    const float* bn1   = (const float*)d_in[7];
    const float* Wn2   = (const float*)d_in[8];
    const float* bn2   = (const float*)d_in[9];
    const int*   esrc  = (const int*)d_in[10];
    const int*   esnk  = (const int*)d_in[11];
    float* out = (float*)d_out;

    k_copy_ns<<<8192, 256>>>(nodes);

    for (int s = 0; s < STEPS; s++) {
        k_zero_inc<<<8192, 256>>>();
        k_edge1<<<dim3(Hh / 128, (Bb * Ee) / 128), 256>>>(We1, be1, esrc, esnk);
        k_edge2<<<dim3(MSGm / 128, (Bb * Ee) / 128), 256>>>(We2, be2, esnk);
        k_node1<<<dim3(Hh / 128, (Bb * Nn) / 128), 256>>>(Wn1, bn1);
        k_node2<<<dim3(2, (Bb * Nn) / 128), 256>>>(Wn2, bn2);
    }

    k_extract<<<dim3(Pp, Bb), 256>>>(attn, out);
}

// round 4
// speedup vs baseline: 2.1565x; 2.1565x over previous
#include <cuda_runtime.h>
#include <cstdint>

// Problem constants (fixed by setup_inputs)
#define Bb   8
#define Nn   4096
#define Ee   16384
#define Pp   64
#define Dd   256
#define Hh   512
#define MSGm 256
#define UPDu 254
#define STEPS 3

#define SMS 136   // smem row stride (words): frag bank = 8*tig+grp, conflict-free

// Scratch (device globals per harness allocation rules)
__device__ __align__(128) float g_ns [(size_t)Bb * Nn * Dd];   //  33.5 MB node states
__device__ __align__(128) float g_h  [(size_t)Bb * Ee * Hh];   // 268   MB edge hidden
__device__ __align__(128) float g_inc[(size_t)Bb * Nn * MSGm]; //  33.5 MB messages
__device__ __align__(128) float g_h2 [(size_t)Bb * Nn * Hh];   //  67   MB node hidden

// ---------------------------------------------------------------------------
__device__ __forceinline__ uint32_t f2tf(float x) {
    uint32_t u;
    asm("cvt.rna.tf32.f32 %0, %1;" : "=r"(u) : "f"(x));
    return u;
}

__device__ __forceinline__ void mma8(float* c, uint32_t a0, uint32_t a1,
                                     uint32_t a2, uint32_t a3,
                                     uint32_t b0, uint32_t b1) {
    asm volatile(
        "mma.sync.aligned.m16n8k8.row.col.f32.tf32.tf32.f32 "
        "{%0,%1,%2,%3}, {%4,%5,%6,%7}, {%8,%9}, {%0,%1,%2,%3};"
        : "+f"(c[0]), "+f"(c[1]), "+f"(c[2]), "+f"(c[3])
        : "r"(a0), "r"(a1), "r"(a2), "r"(a3), "r"(b0), "r"(b1));
}

// ---------------------------------------------------------------------------
__global__ void k_copy_ns(const float* __restrict__ src) {
    size_t i = (size_t)blockIdx.x * blockDim.x + threadIdx.x;
    if (i < ((size_t)Bb * Nn * Dd) / 4) ((float4*)g_ns)[i] = ((const float4*)src)[i];
}

__global__ void k_zero_inc() {
    size_t i = (size_t)blockIdx.x * blockDim.x + threadIdx.x;
    if (i < ((size_t)Bb * Nn * MSGm) / 4)
        ((float4*)g_inc)[i] = make_float4(0.f, 0.f, 0.f, 0.f);
}

// ---------------------------------------------------------------------------
// Each GEMM kernel: 256 threads = 8 warps; block tile 128(M) x 128(N), K-step 16.
// Warp tile 64x32 = 4x4 m16n8k8 mmas.

#define GEMM_PROLOG                                                      \
    const int tid  = threadIdx.x;                                        \
    const int lane = tid & 31;                                           \
    const int warp = tid >> 5;                                           \
    const int grp  = lane >> 2;                                          \
    const int tig  = lane & 3;                                           \
    const int wM   = (warp & 1) * 64;                                    \
    const int wN   = (warp >> 1) * 32;                                   \
    float acc[4][4][4];                                                  \
    _Pragma("unroll") for (int i = 0; i < 4; i++)                        \
    _Pragma("unroll") for (int j = 0; j < 4; j++)                        \
    _Pragma("unroll") for (int q = 0; q < 4; q++) acc[i][j][q] = 0.f;

#define GEMM_MAINLOOP_MMA                                                \
    __syncthreads();                                                     \
    _Pragma("unroll") for (int kb = 0; kb < 16; kb += 8) {               \
        uint32_t af[4][4], bf[4][2];                                     \
        _Pragma("unroll") for (int mt = 0; mt < 4; mt++) {               \
            int r = wM + mt * 16 + grp;                                  \
            af[mt][0] = As[kb + tig][r];                                 \
            af[mt][1] = As[kb + tig][r + 8];                             \
            af[mt][2] = As[kb + tig + 4][r];                             \
            af[mt][3] = As[kb + tig + 4][r + 8];                         \
        }                                                                \
        _Pragma("unroll") for (int nt = 0; nt < 4; nt++) {               \
            int cc = wN + nt * 8 + grp;                                  \
            bf[nt][0] = Bs[kb + tig][cc];                                \
            bf[nt][1] = Bs[kb + tig + 4][cc];                            \
        }                                                                \
        _Pragma("unroll") for (int mt = 0; mt < 4; mt++)                 \
        _Pragma("unroll") for (int nt = 0; nt < 4; nt++)                 \
            mma8(acc[mt][nt], af[mt][0], af[mt][1], af[mt][2],           \
                 af[mt][3], bf[nt][0], bf[nt][1]);                       \
    }                                                                    \
    __syncthreads();

#define A_STORE(q, v)                                                    \
    As[akq + (q)*4 + 0][ar] = f2tf((v).x);                               \
    As[akq + (q)*4 + 1][ar] = f2tf((v).y);                               \
    As[akq + (q)*4 + 2][ar] = f2tf((v).z);                               \
    As[akq + (q)*4 + 3][ar] = f2tf((v).w);

#define B_STORE(q, v)                                                    \
    Bs[bkr][bnq + (q)*4 + 0] = f2tf((v).x);                              \
    Bs[bkr][bnq + (q)*4 + 1] = f2tf((v).y);                              \
    Bs[bkr][bnq + (q)*4 + 2] = f2tf((v).z);                              \
    Bs[bkr][bnq + (q)*4 + 3] = f2tf((v).w);

// ---------------------------------------------------------------------------
// Edge MLP layer 1: g_h = relu(concat(ns[src], ns[snk]) @ W_e1 + b_e1)
// M = B*E = 131072, N = 512, K = 512
__global__ __launch_bounds__(256)
void k_edge1(const float* __restrict__ We1, const float* __restrict__ be1,
             const int* __restrict__ esrc, const int* __restrict__ esnk)
{
    __shared__ uint32_t As[16][SMS];
    __shared__ uint32_t Bs[16][SMS];
    __shared__ int sIdx[2][128];

    GEMM_PROLOG;

    const int rowBase = blockIdx.y * 128;
    const int colBase = blockIdx.x * 128;
    const int b  = rowBase >> 14;
    const int e0 = rowBase & (Ee - 1);

    if (tid < 128)      sIdx[0][tid]       = esrc[e0 + tid];
    else                sIdx[1][tid - 128] = esnk[e0 + tid - 128];
    __syncthreads();

    const float* nsb = g_ns + (size_t)b * Nn * Dd;

    const int ar  = tid >> 1;
    const int akq = (tid & 1) * 8;
    const int bkr = tid >> 4;
    const int bnq = (tid & 15) * 8;

    for (int k0 = 0; k0 < 2 * Dd; k0 += 16) {
#pragma unroll
        for (int q = 0; q < 2; q++) {
            int kg   = k0 + akq + q * 4;
            int half = kg >> 8;
            int idx  = sIdx[half][ar];
            float4 v = *(const float4*)(nsb + (size_t)idx * Dd + (kg & (Dd - 1)));
            A_STORE(q, v);
        }
#pragma unroll
        for (int q = 0; q < 2; q++) {
            float4 v = *(const float4*)(We1 + (size_t)(k0 + bkr) * Hh + colBase + bnq + q * 4);
            B_STORE(q, v);
        }
        GEMM_MAINLOOP_MMA;
    }

#pragma unroll
    for (int mt = 0; mt < 4; mt++) {
        int r0 = rowBase + wM + mt * 16 + grp;
#pragma unroll
        for (int nt = 0; nt < 4; nt++) {
            int c0 = colBase + wN + nt * 8 + tig * 2;
            float b0 = be1[c0], b1 = be1[c0 + 1];
            float* a = acc[mt][nt];
            *(float2*)(g_h + (size_t)r0 * Hh + c0) =
                make_float2(fmaxf(a[0] + b0, 0.f), fmaxf(a[1] + b1, 0.f));
            *(float2*)(g_h + (size_t)(r0 + 8) * Hh + c0) =
                make_float2(fmaxf(a[2] + b0, 0.f), fmaxf(a[3] + b1, 0.f));
        }
    }
}

// ---------------------------------------------------------------------------
// Edge MLP layer 2 + scatter: msgs = g_h @ W_e2 + b_e2; atomic add into g_inc[snk]
// M = 131072, N = 256, K = 512
__global__ __launch_bounds__(256)
void k_edge2(const float* __restrict__ We2, const float* __restrict__ be2,
             const int* __restrict__ esnk)
{
    __shared__ uint32_t As[16][SMS];
    __shared__ uint32_t Bs[16][SMS];
    __shared__ int sSnk[128];

    GEMM_PROLOG;

    const int rowBase = blockIdx.y * 128;
    const int colBase = blockIdx.x * 128;
    const int b  = rowBase >> 14;
    const int e0 = rowBase & (Ee - 1);

    if (tid < 128) sSnk[tid] = esnk[e0 + tid];
    __syncthreads();

    const float* A = g_h + (size_t)rowBase * Hh;

    const int ar  = tid >> 1;
    const int akq = (tid & 1) * 8;
    const int bkr = tid >> 4;
    const int bnq = (tid & 15) * 8;

    for (int k0 = 0; k0 < Hh; k0 += 16) {
#pragma unroll
        for (int q = 0; q < 2; q++) {
            float4 v = *(const float4*)(A + (size_t)ar * Hh + k0 + akq + q * 4);
            A_STORE(q, v);
        }
#pragma unroll
        for (int q = 0; q < 2; q++) {
            float4 v = *(const float4*)(We2 + (size_t)(k0 + bkr) * MSGm + colBase + bnq + q * 4);
            B_STORE(q, v);
        }
        GEMM_MAINLOOP_MMA;
    }

    float* incb = g_inc + (size_t)b * Nn * MSGm;
#pragma unroll
    for (int mt = 0; mt < 4; mt++) {
        int r0 = wM + mt * 16 + grp;
        int s0 = sSnk[r0], s1 = sSnk[r0 + 8];
#pragma unroll
        for (int nt = 0; nt < 4; nt++) {
            int c0 = colBase + wN + nt * 8 + tig * 2;
            float b0 = be2[c0], b1 = be2[c0 + 1];
            float* a = acc[mt][nt];
            float* p0 = incb + (size_t)s0 * MSGm + c0;
            float* p1 = incb + (size_t)s1 * MSGm + c0;
            atomicAdd(p0,     a[0] + b0);
            atomicAdd(p0 + 1, a[1] + b1);
            atomicAdd(p1,     a[2] + b0);
            atomicAdd(p1 + 1, a[3] + b1);
        }
    }
}

// ---------------------------------------------------------------------------
// Node MLP layer 1: g_h2 = relu(concat(g_inc, g_ns) @ W_n1 + b_n1)
// M = B*N = 32768, N = 512, K = 512
__global__ __launch_bounds__(256)
void k_node1(const float* __restrict__ Wn1, const float* __restrict__ bn1)
{
    __shared__ uint32_t As[16][SMS];
    __shared__ uint32_t Bs[16][SMS];

    GEMM_PROLOG;

    const int rowBase = blockIdx.y * 128;
    const int colBase = blockIdx.x * 128;

    const int ar  = tid >> 1;
    const int akq = (tid & 1) * 8;
    const int bkr = tid >> 4;
    const int bnq = (tid & 15) * 8;

    for (int k0 = 0; k0 < Dd + MSGm; k0 += 16) {
#pragma unroll
        for (int q = 0; q < 2; q++) {
            int kg = k0 + akq + q * 4;
            const float* src = (kg < MSGm)
                ? (g_inc + (size_t)(rowBase + ar) * MSGm + kg)
                : (g_ns  + (size_t)(rowBase + ar) * Dd + (kg - MSGm));
            float4 v = *(const float4*)src;
            A_STORE(q, v);
        }
#pragma unroll
        for (int q = 0; q < 2; q++) {
            float4 v = *(const float4*)(Wn1 + (size_t)(k0 + bkr) * Hh + colBase + bnq + q * 4);
            B_STORE(q, v);
        }
        GEMM_MAINLOOP_MMA;
    }

#pragma unroll
    for (int mt = 0; mt < 4; mt++) {
        int r0 = rowBase + wM + mt * 16 + grp;
#pragma unroll
        for (int nt = 0; nt < 4; nt++) {
            int c0 = colBase + wN + nt * 8 + tig * 2;
            float b0 = bn1[c0], b1 = bn1[c0 + 1];
            float* a = acc[mt][nt];
            *(float2*)(g_h2 + (size_t)r0 * Hh + c0) =
                make_float2(fmaxf(a[0] + b0, 0.f), fmaxf(a[1] + b1, 0.f));
            *(float2*)(g_h2 + (size_t)(r0 + 8) * Hh + c0) =
                make_float2(fmaxf(a[2] + b0, 0.f), fmaxf(a[3] + b1, 0.f));
        }
    }
}

// ---------------------------------------------------------------------------
// Node MLP layer 2 + in-place update: g_ns[:, 2+c] += (g_h2 @ W_n2 + b_n2)[c]
// M = 32768, N = 254 (padded 256), K = 512
__global__ __launch_bounds__(256)
void k_node2(const float* __restrict__ Wn2, const float* __restrict__ bn2)
{
    __shared__ uint32_t As[16][SMS];
    __shared__ uint32_t Bs[16][SMS];

    GEMM_PROLOG;

    const int rowBase = blockIdx.y * 128;
    const int colBase = blockIdx.x * 128;

    const int ar  = tid >> 1;
    const int akq = (tid & 1) * 8;
    const int bkr = tid >> 4;
    const int bnq = (tid & 15) * 8;

    const float* A = g_h2 + (size_t)rowBase * Hh;

    for (int k0 = 0; k0 < Hh; k0 += 16) {
#pragma unroll
        for (int q = 0; q < 2; q++) {
            float4 v = *(const float4*)(A + (size_t)ar * Hh + k0 + akq + q * 4);
            A_STORE(q, v);
        }
        // B rows have stride 254 (unaligned) -> guarded scalar loads
#pragma unroll
        for (int j = 0; j < 8; j++) {
            int c = colBase + bnq + j;
            Bs[bkr][bnq + j] = (c < UPDu)
                ? f2tf(Wn2[(size_t)(k0 + bkr) * UPDu + c]) : 0u;
        }
        GEMM_MAINLOOP_MMA;
    }

#pragma unroll
    for (int mt = 0; mt < 4; mt++) {
        int r0 = rowBase + wM + mt * 16 + grp;
#pragma unroll
        for (int nt = 0; nt < 4; nt++) {
            int c0 = colBase + wN + nt * 8 + tig * 2;
            float* a = acc[mt][nt];
            if (c0 + 1 < UPDu) {
                float b0 = bn2[c0], b1 = bn2[c0 + 1];
                float* p0 = g_ns + (size_t)r0 * Dd + 2 + c0;
                float* p1 = g_ns + (size_t)(r0 + 8) * Dd + 2 + c0;
                float2 o0 = *(float2*)p0, o1 = *(float2*)p1;
                *(float2*)p0 = make_float2(o0.x + a[0] + b0, o0.y + a[1] + b1);
                *(float2*)p1 = make_float2(o1.x + a[2] + b0, o1.y + a[3] + b1);
            } else if (c0 < UPDu) {
                float b0 = bn2[c0];
                g_ns[(size_t)r0 * Dd + 2 + c0]       += a[0] + b0;
                g_ns[(size_t)(r0 + 8) * Dd + 2 + c0] += a[2] + b0;
            }
        }
    }
}

// ---------------------------------------------------------------------------
// Extraction: out[b,p,d] = sum_n attn[b,p,n] * ns[b,n,d]
__global__ __launch_bounds__(256)
void k_extract(const float* __restrict__ attn, float* __restrict__ out)
{
    const int p = blockIdx.x;
    const int b = blockIdx.y;
    const int d = threadIdx.x;

    const float* ap  = attn + ((size_t)b * Pp + p) * Nn;
    const float* nsb = g_ns + (size_t)b * Nn * Dd;

    __shared__ float sa[256];
    float acc0 = 0.f, acc1 = 0.f;
    for (int n0 = 0; n0 < Nn; n0 += 256) {
        __syncthreads();
        sa[d] = ap[n0 + d];
        __syncthreads();
#pragma unroll 8
        for (int n = 0; n < 256; n += 2) {
            acc0 = fmaf(sa[n],     nsb[(size_t)(n0 + n) * Dd + d],     acc0);
            acc1 = fmaf(sa[n + 1], nsb[(size_t)(n0 + n + 1) * Dd + d], acc1);
        }
    }
    out[((size_t)b * Pp + p) * Dd + d] = acc0 + acc1;
}

// ---------------------------------------------------------------------------
extern "C" void kernel_launch(void* const* d_in, const int* in_sizes, int n_in,
                              void* d_out, int out_size)
{
    const float* nodes = (const float*)d_in[0];
    const float* attn  = (const float*)d_in[1];
    const float* We1   = (const float*)d_in[2];
    const float* be1   = (const float*)d_in[3];
    const float* We2   = (const float*)d_in[4];
    const float* be2   = (const float*)d_in[5];
    const float* Wn1   = (const float*)d_in[6];
    const float* bn1   = (const float*)d_in[7];
    const float* Wn2   = (const float*)d_in[8];
    const float* bn2   = (const float*)d_in[9];
    const int*   esrc  = (const int*)d_in[10];
    const int*   esnk  = (const int*)d_in[11];
    float* out = (float*)d_out;

    k_copy_ns<<<8192, 256>>>(nodes);

    for (int s = 0; s < STEPS; s++) {
        k_zero_inc<<<8192, 256>>>();
        k_edge1<<<dim3(Hh / 128,  (Bb * Ee) / 128), 256>>>(We1, be1, esrc, esnk);
        k_edge2<<<dim3(MSGm / 128, (Bb * Ee) / 128), 256>>>(We2, be2, esnk);
        k_node1<<<dim3(Hh / 128,  (Bb * Nn) / 128), 256>>>(Wn1, bn1);
        k_node2<<<dim3(2,         (Bb * Nn) / 128), 256>>>(Wn2, bn2);
    }

    k_extract<<<dim3(Pp, Bb), 256>>>(attn, out);
}

// round 8
// speedup vs baseline: 2.4975x; 1.1581x over previous
#include <cuda_runtime.h>
#include <cstdint>

// Problem constants (fixed by setup_inputs)
#define Bb   8
#define Nn   4096
#define Ee   16384
#define Pp   64
#define Dd   256
#define Hh   512
#define MSGm 256
#define UPDu 254
#define STEPS 3

#define SKA  20    // A smem row stride (words): frag bank 20*grp+tig covers 32 banks
#define SKB  136   // B smem row stride (words): frag bank 136*tig+grp covers 32 banks

// Scratch (device globals per harness allocation rules)
__device__ __align__(128) float g_ns [(size_t)Bb * Nn * Dd];
__device__ __align__(128) float g_h  [(size_t)Bb * Ee * Hh];
__device__ __align__(128) float g_inc[(size_t)Bb * Nn * MSGm];
__device__ __align__(128) float g_h2 [(size_t)Bb * Nn * Hh];

// ---------------------------------------------------------------------------
__device__ __forceinline__ uint32_t f2tf(float x) {
    uint32_t u;
    asm("cvt.rna.tf32.f32 %0, %1;" : "=r"(u) : "f"(x));
    return u;
}

__device__ __forceinline__ void mma8(float* c, uint32_t a0, uint32_t a1,
                                     uint32_t a2, uint32_t a3,
                                     uint32_t b0, uint32_t b1) {
    asm volatile(
        "mma.sync.aligned.m16n8k8.row.col.f32.tf32.tf32.f32 "
        "{%0,%1,%2,%3}, {%4,%5,%6,%7}, {%8,%9}, {%0,%1,%2,%3};"
        : "+f"(c[0]), "+f"(c[1]), "+f"(c[2]), "+f"(c[3])
        : "r"(a0), "r"(a1), "r"(a2), "r"(a3), "r"(b0), "r"(b1));
}

__device__ __forceinline__ void cpa16(uint32_t dst, const float* src) {
    asm volatile("cp.async.ca.shared.global [%0], [%1], 16;"
                 :: "r"(dst), "l"(src));
}
__device__ __forceinline__ void cpa4z(uint32_t dst, const float* src, int ok) {
    asm volatile("cp.async.ca.shared.global [%0], [%1], 4, %2;"
                 :: "r"(dst), "l"(src), "r"(ok ? 4 : 0));
}
#define CP_COMMIT asm volatile("cp.async.commit_group;")
#define CP_WAIT1  asm volatile("cp.async.wait_group 1;")
#define CP_WAIT0  asm volatile("cp.async.wait_group 0;")

// ---------------------------------------------------------------------------
__global__ void k_copy_ns(const float* __restrict__ src) {
    size_t i = (size_t)blockIdx.x * blockDim.x + threadIdx.x;
    if (i < ((size_t)Bb * Nn * Dd) / 4) ((float4*)g_ns)[i] = ((const float4*)src)[i];
}

__global__ void k_zero_inc() {
    size_t i = (size_t)blockIdx.x * blockDim.x + threadIdx.x;
    if (i < ((size_t)Bb * Nn * MSGm) / 4)
        ((float4*)g_inc)[i] = make_float4(0.f, 0.f, 0.f, 0.f);
}

// ---------------------------------------------------------------------------
// 256 threads = 8 warps; block tile 128(M) x 128(N), K-step 16, 2-stage cp.async.
// Warp tile 64x32 = 4x4 m16n8k8 mmas. Raw fp32 in smem; cvt.rna.tf32 applied
// at fragment-load time (same rounding as the R4 passing kernel).

#define GEMM_PROLOG                                                      \
    const int tid  = threadIdx.x;                                        \
    const int lane = tid & 31;                                           \
    const int warp = tid >> 5;                                           \
    const int grp  = lane >> 2;                                          \
    const int tig  = lane & 3;                                           \
    const int wM   = (warp & 1) * 64;                                    \
    const int wN   = (warp >> 1) * 32;                                   \
    const int ar   = tid >> 1;            /* A row 0..127 */             \
    const int akq  = (tid & 1) * 8;       /* A k chunk 0/8 */            \
    const int bkr  = tid >> 4;            /* B k row 0..15 */            \
    const int bnq  = (tid & 15) * 8;      /* B n chunk */                \
    const uint32_t sA = (uint32_t)__cvta_generic_to_shared(&As[0][0][0]);\
    const uint32_t sB = (uint32_t)__cvta_generic_to_shared(&Bs[0][0][0]);\
    float acc[4][4][4];                                                  \
    _Pragma("unroll") for (int i = 0; i < 4; i++)                        \
    _Pragma("unroll") for (int j = 0; j < 4; j++)                        \
    _Pragma("unroll") for (int q = 0; q < 4; q++) acc[i][j][q] = 0.f;

#define A_ADDR(st, m, k) (sA + (((st) * 128 + (m)) * SKA + (k)) * 4u)
#define B_ADDR(st, k, n) (sB + (((st) * 16  + (k)) * SKB + (n)) * 4u)

#define COMPUTE(st)                                                      \
    _Pragma("unroll") for (int kb = 0; kb < 16; kb += 8) {               \
        uint32_t af[4][4], bf[4][2];                                     \
        _Pragma("unroll") for (int mt = 0; mt < 4; mt++) {               \
            int r = wM + mt * 16 + grp;                                  \
            af[mt][0] = f2tf(As[st][r][kb + tig]);                       \
            af[mt][1] = f2tf(As[st][r + 8][kb + tig]);                   \
            af[mt][2] = f2tf(As[st][r][kb + tig + 4]);                   \
            af[mt][3] = f2tf(As[st][r + 8][kb + tig + 4]);               \
        }                                                                \
        _Pragma("unroll") for (int nt = 0; nt < 4; nt++) {               \
            int cc = wN + nt * 8 + grp;                                  \
            bf[nt][0] = f2tf(Bs[st][kb + tig][cc]);                      \
            bf[nt][1] = f2tf(Bs[st][kb + tig + 4][cc]);                  \
        }                                                                \
        _Pragma("unroll") for (int mt = 0; mt < 4; mt++)                 \
        _Pragma("unroll") for (int nt = 0; nt < 4; nt++)                 \
            mma8(acc[mt][nt], af[mt][0], af[mt][1], af[mt][2],           \
                 af[mt][3], bf[nt][0], bf[nt][1]);                       \
    }

// Pipeline driver: LOADER(st, k0) issues cp.async for one stage.
#define PIPELINE(NITER, LOADER)                                          \
    LOADER(0, 0);                                                        \
    CP_COMMIT;                                                           \
    for (int it = 0; it < (NITER); it++) {                               \
        if (it + 1 < (NITER)) {                                          \
            LOADER((it + 1) & 1, (it + 1) * 16);                         \
            CP_COMMIT;                                                   \
            CP_WAIT1;                                                    \
        } else {                                                         \
            CP_WAIT0;                                                    \
        }                                                                \
        __syncthreads();                                                 \
        COMPUTE(it & 1);                                                 \
        __syncthreads();                                                 \
    }

#define SMEM_TILES                                                       \
    __shared__ float As[2][128][SKA];                                    \
    __shared__ float Bs[2][16][SKB];

// ---------------------------------------------------------------------------
// Edge MLP layer 1: g_h = relu(concat(ns[src], ns[snk]) @ W_e1 + b_e1)
// M = 131072, N = 512, K = 512
__global__ __launch_bounds__(256, 2)
void k_edge1(const float* __restrict__ We1, const float* __restrict__ be1,
             const int* __restrict__ esrc, const int* __restrict__ esnk)
{
    SMEM_TILES;
    __shared__ int sIdx[2][128];

    GEMM_PROLOG;

    const int rowBase = blockIdx.y * 128;
    const int colBase = blockIdx.x * 128;
    const int b  = rowBase >> 14;
    const int e0 = rowBase & (Ee - 1);

    if (tid < 128)      sIdx[0][tid]       = esrc[e0 + tid];
    else                sIdx[1][tid - 128] = esnk[e0 + tid - 128];
    __syncthreads();

    const float* nsb = g_ns + (size_t)b * Nn * Dd;

#define LOAD_E1(st, k0)                                                  \
    {                                                                    \
        _Pragma("unroll") for (int q = 0; q < 2; q++) {                  \
            int kg = (k0) + akq + q * 4;                                 \
            int idx = sIdx[kg >> 8][ar];                                 \
            cpa16(A_ADDR(st, ar, akq + q * 4),                           \
                  nsb + (size_t)idx * Dd + (kg & (Dd - 1)));             \
        }                                                                \
        _Pragma("unroll") for (int q = 0; q < 2; q++)                    \
            cpa16(B_ADDR(st, bkr, bnq + q * 4),                          \
                  We1 + (size_t)((k0) + bkr) * Hh + colBase + bnq + q * 4); \
    }

    PIPELINE(32, LOAD_E1);

#pragma unroll
    for (int mt = 0; mt < 4; mt++) {
        int r0 = rowBase + wM + mt * 16 + grp;
#pragma unroll
        for (int nt = 0; nt < 4; nt++) {
            int c0 = colBase + wN + nt * 8 + tig * 2;
            float b0 = be1[c0], b1 = be1[c0 + 1];
            float* a = acc[mt][nt];
            *(float2*)(g_h + (size_t)r0 * Hh + c0) =
                make_float2(fmaxf(a[0] + b0, 0.f), fmaxf(a[1] + b1, 0.f));
            *(float2*)(g_h + (size_t)(r0 + 8) * Hh + c0) =
                make_float2(fmaxf(a[2] + b0, 0.f), fmaxf(a[3] + b1, 0.f));
        }
    }
}

// ---------------------------------------------------------------------------
// Edge MLP layer 2 + scatter: msgs = g_h @ W_e2 + b_e2; atomic add into g_inc
// M = 131072, N = 256, K = 512
__global__ __launch_bounds__(256, 2)
void k_edge2(const float* __restrict__ We2, const float* __restrict__ be2,
             const int* __restrict__ esnk)
{
    SMEM_TILES;
    __shared__ int sSnk[128];

    GEMM_PROLOG;

    const int rowBase = blockIdx.y * 128;
    const int colBase = blockIdx.x * 128;
    const int b  = rowBase >> 14;
    const int e0 = rowBase & (Ee - 1);

    if (tid < 128) sSnk[tid] = esnk[e0 + tid];
    __syncthreads();

    const float* Ag = g_h + (size_t)rowBase * Hh;

#define LOAD_E2(st, k0)                                                  \
    {                                                                    \
        _Pragma("unroll") for (int q = 0; q < 2; q++)                    \
            cpa16(A_ADDR(st, ar, akq + q * 4),                           \
                  Ag + (size_t)ar * Hh + (k0) + akq + q * 4);            \
        _Pragma("unroll") for (int q = 0; q < 2; q++)                    \
            cpa16(B_ADDR(st, bkr, bnq + q * 4),                          \
                  We2 + (size_t)((k0) + bkr) * MSGm + colBase + bnq + q * 4); \
    }

    PIPELINE(32, LOAD_E2);

    float* incb = g_inc + (size_t)b * Nn * MSGm;
#pragma unroll
    for (int mt = 0; mt < 4; mt++) {
        int r0 = wM + mt * 16 + grp;
        int s0 = sSnk[r0], s1 = sSnk[r0 + 8];
#pragma unroll
        for (int nt = 0; nt < 4; nt++) {
            int c0 = colBase + wN + nt * 8 + tig * 2;
            float b0 = be2[c0], b1 = be2[c0 + 1];
            float* a = acc[mt][nt];
            float* p0 = incb + (size_t)s0 * MSGm + c0;
            float* p1 = incb + (size_t)s1 * MSGm + c0;
            atomicAdd(p0,     a[0] + b0);
            atomicAdd(p0 + 1, a[1] + b1);
            atomicAdd(p1,     a[2] + b0);
            atomicAdd(p1 + 1, a[3] + b1);
        }
    }
}

// ---------------------------------------------------------------------------
// Node MLP layer 1: g_h2 = relu(concat(g_inc, g_ns) @ W_n1 + b_n1)
// M = 32768, N = 512, K = 512
__global__ __launch_bounds__(256, 2)
void k_node1(const float* __restrict__ Wn1, const float* __restrict__ bn1)
{
    SMEM_TILES;

    GEMM_PROLOG;

    const int rowBase = blockIdx.y * 128;
    const int colBase = blockIdx.x * 128;

#define LOAD_N1(st, k0)                                                  \
    {                                                                    \
        _Pragma("unroll") for (int q = 0; q < 2; q++) {                  \
            int kg = (k0) + akq + q * 4;                                 \
            const float* src = (kg < MSGm)                               \
                ? (g_inc + (size_t)(rowBase + ar) * MSGm + kg)           \
                : (g_ns  + (size_t)(rowBase + ar) * Dd + (kg - MSGm));   \
            cpa16(A_ADDR(st, ar, akq + q * 4), src);                     \
        }                                                                \
        _Pragma("unroll") for (int q = 0; q < 2; q++)                    \
            cpa16(B_ADDR(st, bkr, bnq + q * 4),                          \
                  Wn1 + (size_t)((k0) + bkr) * Hh + colBase + bnq + q * 4); \
    }

    PIPELINE(32, LOAD_N1);

#pragma unroll
    for (int mt = 0; mt < 4; mt++) {
        int r0 = rowBase + wM + mt * 16 + grp;
#pragma unroll
        for (int nt = 0; nt < 4; nt++) {
            int c0 = colBase + wN + nt * 8 + tig * 2;
            float b0 = bn1[c0], b1 = bn1[c0 + 1];
            float* a = acc[mt][nt];
            *(float2*)(g_h2 + (size_t)r0 * Hh + c0) =
                make_float2(fmaxf(a[0] + b0, 0.f), fmaxf(a[1] + b1, 0.f));
            *(float2*)(g_h2 + (size_t)(r0 + 8) * Hh + c0) =
                make_float2(fmaxf(a[2] + b0, 0.f), fmaxf(a[3] + b1, 0.f));
        }
    }
}

// ---------------------------------------------------------------------------
// Node MLP layer 2 + in-place update: g_ns[:, 2+c] += (g_h2 @ W_n2 + b_n2)[c]
// M = 32768, N = 254 (padded 256), K = 512
__global__ __launch_bounds__(256, 2)
void k_node2(const float* __restrict__ Wn2, const float* __restrict__ bn2)
{
    SMEM_TILES;

    GEMM_PROLOG;

    const int rowBase = blockIdx.y * 128;
    const int colBase = blockIdx.x * 128;

    const float* Ag = g_h2 + (size_t)rowBase * Hh;

#define LOAD_N2(st, k0)                                                  \
    {                                                                    \
        _Pragma("unroll") for (int q = 0; q < 2; q++)                    \
            cpa16(A_ADDR(st, ar, akq + q * 4),                           \
                  Ag + (size_t)ar * Hh + (k0) + akq + q * 4);            \
        _Pragma("unroll") for (int j = 0; j < 8; j++) {                  \
            int c = colBase + bnq + j;                                   \
            int ok = (c < UPDu);                                         \
            const float* src = ok                                        \
                ? (Wn2 + (size_t)((k0) + bkr) * UPDu + c) : Wn2;         \
            cpa4z(B_ADDR(st, bkr, bnq + j), src, ok);                    \
        }                                                                \
    }

    PIPELINE(32, LOAD_N2);

#pragma unroll
    for (int mt = 0; mt < 4; mt++) {
        int r0 = rowBase + wM + mt * 16 + grp;
#pragma unroll
        for (int nt = 0; nt < 4; nt++) {
            int c0 = colBase + wN + nt * 8 + tig * 2;
            float* a = acc[mt][nt];
            if (c0 + 1 < UPDu) {
                float b0 = bn2[c0], b1 = bn2[c0 + 1];
                float* p0 = g_ns + (size_t)r0 * Dd + 2 + c0;
                float* p1 = g_ns + (size_t)(r0 + 8) * Dd + 2 + c0;
                float2 o0 = *(float2*)p0, o1 = *(float2*)p1;
                *(float2*)p0 = make_float2(o0.x + a[0] + b0, o0.y + a[1] + b1);
                *(float2*)p1 = make_float2(o1.x + a[2] + b0, o1.y + a[3] + b1);
            } else if (c0 < UPDu) {
                float b0 = bn2[c0];
                g_ns[(size_t)r0 * Dd + 2 + c0]       += a[0] + b0;
                g_ns[(size_t)(r0 + 8) * Dd + 2 + c0] += a[2] + b0;
            }
        }
    }
}

// ---------------------------------------------------------------------------
// Extraction: out[b,p,d] = sum_n attn[b,p,n] * ns[b,n,d]
__global__ __launch_bounds__(256)
void k_extract(const float* __restrict__ attn, float* __restrict__ out)
{
    const int p = blockIdx.x;
    const int b = blockIdx.y;
    const int d = threadIdx.x;

    const float* ap  = attn + ((size_t)b * Pp + p) * Nn;
    const float* nsb = g_ns + (size_t)b * Nn * Dd;

    __shared__ float sa[256];
    float acc0 = 0.f, acc1 = 0.f;
    for (int n0 = 0; n0 < Nn; n0 += 256) {
        __syncthreads();
        sa[d] = ap[n0 + d];
        __syncthreads();
#pragma unroll 8
        for (int n = 0; n < 256; n += 2) {
            acc0 = fmaf(sa[n],     nsb[(size_t)(n0 + n) * Dd + d],     acc0);
            acc1 = fmaf(sa[n + 1], nsb[(size_t)(n0 + n + 1) * Dd + d], acc1);
        }
    }
    out[((size_t)b * Pp + p) * Dd + d] = acc0 + acc1;
}

// ---------------------------------------------------------------------------
extern "C" void kernel_launch(void* const* d_in, const int* in_sizes, int n_in,
                              void* d_out, int out_size)
{
    const float* nodes = (const float*)d_in[0];
    const float* attn  = (const float*)d_in[1];
    const float* We1   = (const float*)d_in[2];
    const float* be1   = (const float*)d_in[3];
    const float* We2   = (const float*)d_in[4];
    const float* be2   = (const float*)d_in[5];
    const float* Wn1   = (const float*)d_in[6];
    const float* bn1   = (const float*)d_in[7];
    const float* Wn2   = (const float*)d_in[8];
    const float* bn2   = (const float*)d_in[9];
    const int*   esrc  = (const int*)d_in[10];
    const int*   esnk  = (const int*)d_in[11];
    float* out = (float*)d_out;

    k_copy_ns<<<8192, 256>>>(nodes);

    for (int s = 0; s < STEPS; s++) {
        k_zero_inc<<<8192, 256>>>();
        k_edge1<<<dim3(Hh / 128,  (Bb * Ee) / 128), 256>>>(We1, be1, esrc, esnk);
        k_edge2<<<dim3(MSGm / 128, (Bb * Ee) / 128), 256>>>(We2, be2, esnk);
        k_node1<<<dim3(Hh / 128,  (Bb * Nn) / 128), 256>>>(Wn1, bn1);
        k_node2<<<dim3(2,         (Bb * Nn) / 128), 256>>>(Wn2, bn2);
    }

    k_extract<<<dim3(Pp, Bb), 256>>>(attn, out);
}

// round 10
// speedup vs baseline: 2.5751x; 1.0311x over previous
#include <cuda_runtime.h>
#include <cstdint>

// Problem constants (fixed by setup_inputs)
#define Bb   8
#define Nn   4096
#define Ee   16384
#define Pp   64
#define Dd   256
#define Hh   512
#define MSGm 256
#define UPDu 254
#define STEPS 3

#define SKA  20    // A smem row stride (words): LDSM rows stride-20 conflict-free
#define SKB  136   // B smem row stride (words): frag bank 8*tig+grp conflict-free

// Scratch (device globals per harness allocation rules)
__device__ __align__(128) float g_ns  [(size_t)Bb * Nn * Dd];   // exact state
__device__ __align__(128) float g_nsr [(size_t)Bb * Nn * Dd];   // tf32-rounded state
__device__ __align__(128) float g_h   [(size_t)Bb * Ee * Hh];   // rounded edge hidden
__device__ __align__(128) float g_inc [(size_t)Bb * Nn * MSGm]; // messages
__device__ __align__(128) float g_h2  [(size_t)Bb * Nn * Hh];   // rounded node hidden
__device__ __align__(128) float g_We1r[(size_t)(2*Dd) * Hh];
__device__ __align__(128) float g_We2r[(size_t)Hh * MSGm];
__device__ __align__(128) float g_Wn1r[(size_t)(Dd+MSGm) * Hh];
__device__ __align__(128) float g_Wn2r[(size_t)Hh * 256];       // padded 254 -> 256

// ---------------------------------------------------------------------------
__device__ __forceinline__ uint32_t f2tf(float x) {
    uint32_t u;
    asm("cvt.rna.tf32.f32 %0, %1;" : "=r"(u) : "f"(x));
    return u;
}
__device__ __forceinline__ float rndf(float x) { return __uint_as_float(f2tf(x)); }

__device__ __forceinline__ void mma8(float* c, uint32_t a0, uint32_t a1,
                                     uint32_t a2, uint32_t a3,
                                     uint32_t b0, uint32_t b1) {
    asm volatile(
        "mma.sync.aligned.m16n8k8.row.col.f32.tf32.tf32.f32 "
        "{%0,%1,%2,%3}, {%4,%5,%6,%7}, {%8,%9}, {%0,%1,%2,%3};"
        : "+f"(c[0]), "+f"(c[1]), "+f"(c[2]), "+f"(c[3])
        : "r"(a0), "r"(a1), "r"(a2), "r"(a3), "r"(b0), "r"(b1));
}

__device__ __forceinline__ void ldsm4(uint32_t& r0, uint32_t& r1,
                                      uint32_t& r2, uint32_t& r3, uint32_t addr) {
    asm volatile("ldmatrix.sync.aligned.m8n8.x4.shared.b16 {%0,%1,%2,%3}, [%4];"
                 : "=r"(r0), "=r"(r1), "=r"(r2), "=r"(r3) : "r"(addr));
}

__device__ __forceinline__ void cpa16(uint32_t dst, const float* src) {
    asm volatile("cp.async.ca.shared.global [%0], [%1], 16;"
                 :: "r"(dst), "l"(src));
}
#define CP_COMMIT asm volatile("cp.async.commit_group;")
#define CP_WAIT1  asm volatile("cp.async.wait_group 1;")
#define CP_WAIT0  asm volatile("cp.async.wait_group 0;")

// ---------------------------------------------------------------------------
// Prologue / utility kernels
__global__ void k_round(const float* __restrict__ src, float* __restrict__ dst, int n) {
    int i = blockIdx.x * blockDim.x + threadIdx.x;
    if (i < n) dst[i] = rndf(src[i]);
}

__global__ void k_round_pad_wn2(const float* __restrict__ src) {
    int i = blockIdx.x * blockDim.x + threadIdx.x;   // over Hh*256
    if (i < Hh * 256) {
        int r = i >> 8, c = i & 255;
        g_Wn2r[i] = (c < UPDu) ? rndf(src[r * UPDu + c]) : 0.f;
    }
}

__global__ void k_copy_ns(const float* __restrict__ src) {
    size_t i = (size_t)blockIdx.x * blockDim.x + threadIdx.x;
    if (i < (size_t)Bb * Nn * Dd) {
        float v = src[i];
        g_ns[i]  = v;
        g_nsr[i] = rndf(v);
    }
}

__global__ void k_zero_inc() {
    size_t i = (size_t)blockIdx.x * blockDim.x + threadIdx.x;
    if (i < ((size_t)Bb * Nn * MSGm) / 4)
        ((float4*)g_inc)[i] = make_float4(0.f, 0.f, 0.f, 0.f);
}

__global__ void k_round_inc() {
    size_t i = (size_t)blockIdx.x * blockDim.x + threadIdx.x;
    if (i < (size_t)Bb * Nn * MSGm) g_inc[i] = rndf(g_inc[i]);
}

// ---------------------------------------------------------------------------
// 256 threads = 8 warps; block tile 128(M) x 128(N), K-step 16, 2-stage cp.async.
// Warp tile 64x32 = 4x4 m16n8k8 mmas. All operands pre-rounded to tf32 in gmem;
// mainloop is pure LDSM/LDS + HMMA (no CVT).

#define GEMM_PROLOG                                                      \
    const int tid  = threadIdx.x;                                        \
    const int lane = tid & 31;                                           \
    const int warp = tid >> 5;                                           \
    const int grp  = lane >> 2;                                          \
    const int tig  = lane & 3;                                           \
    const int wM   = (warp & 1) * 64;                                    \
    const int wN   = (warp >> 1) * 32;                                   \
    const int ar   = tid >> 1;            /* A row 0..127 */             \
    const int akq  = (tid & 1) * 8;       /* A k chunk 0/8 */            \
    const int bkr  = tid >> 4;            /* B k row 0..15 */            \
    const int bnq  = (tid & 15) * 8;      /* B n chunk */                \
    const int lrow = lane & 15;           /* LDSM row-in-tile */         \
    const int lcol = (lane >> 4) * 4;     /* LDSM col offset */          \
    const uint32_t sA = (uint32_t)__cvta_generic_to_shared(&As[0][0][0]);\
    const uint32_t sB = (uint32_t)__cvta_generic_to_shared(&Bs[0][0][0]);\
    float acc[4][4][4];                                                  \
    _Pragma("unroll") for (int i = 0; i < 4; i++)                        \
    _Pragma("unroll") for (int j = 0; j < 4; j++)                        \
    _Pragma("unroll") for (int q = 0; q < 4; q++) acc[i][j][q] = 0.f;

#define A_ADDR(st, m, k) (sA + (((st) * 128 + (m)) * SKA + (k)) * 4u)
#define B_ADDR(st, k, n) (sB + (((st) * 16  + (k)) * SKB + (n)) * 4u)

#define COMPUTE(st)                                                      \
    _Pragma("unroll") for (int kb = 0; kb < 16; kb += 8) {               \
        uint32_t af[4][4], bf[4][2];                                     \
        _Pragma("unroll") for (int mt = 0; mt < 4; mt++)                 \
            ldsm4(af[mt][0], af[mt][1], af[mt][2], af[mt][3],            \
                  A_ADDR(st, wM + mt * 16 + lrow, kb + lcol));           \
        _Pragma("unroll") for (int nt = 0; nt < 4; nt++) {               \
            int cc = wN + nt * 8 + grp;                                  \
            bf[nt][0] = Bs[st][kb + tig][cc];                            \
            bf[nt][1] = Bs[st][kb + tig + 4][cc];                        \
        }                                                                \
        _Pragma("unroll") for (int mt = 0; mt < 4; mt++)                 \
        _Pragma("unroll") for (int nt = 0; nt < 4; nt++)                 \
            mma8(acc[mt][nt], af[mt][0], af[mt][1], af[mt][2],           \
                 af[mt][3], bf[nt][0], bf[nt][1]);                       \
    }

#define PIPELINE(NITER, LOADER)                                          \
    LOADER(0, 0);                                                        \
    CP_COMMIT;                                                           \
    for (int it = 0; it < (NITER); it++) {                               \
        if (it + 1 < (NITER)) {                                          \
            LOADER((it + 1) & 1, (it + 1) * 16);                         \
            CP_COMMIT;                                                   \
            CP_WAIT1;                                                    \
        } else {                                                         \
            CP_WAIT0;                                                    \
        }                                                                \
        __syncthreads();                                                 \
        COMPUTE(it & 1);                                                 \
        __syncthreads();                                                 \
    }

#define SMEM_TILES                                                       \
    __shared__ uint32_t As[2][128][SKA];                                 \
    __shared__ uint32_t Bs[2][16][SKB];

// ---------------------------------------------------------------------------
// Edge MLP layer 1: g_h = rna(relu(concat(nsr[src], nsr[snk]) @ We1r + be1))
// M = 131072, N = 512, K = 512
__global__ __launch_bounds__(256, 2)
void k_edge1(const float* __restrict__ be1,
             const int* __restrict__ esrc, const int* __restrict__ esnk)
{
    SMEM_TILES;
    __shared__ int sIdx[2][128];

    GEMM_PROLOG;

    const int rowBase = blockIdx.y * 128;
    const int colBase = blockIdx.x * 128;
    const int b  = rowBase >> 14;
    const int e0 = rowBase & (Ee - 1);

    if (tid < 128)      sIdx[0][tid]       = esrc[e0 + tid];
    else                sIdx[1][tid - 128] = esnk[e0 + tid - 128];
    __syncthreads();

    const float* nsb = g_nsr + (size_t)b * Nn * Dd;

#define LOAD_E1(st, k0)                                                  \
    {                                                                    \
        _Pragma("unroll") for (int q = 0; q < 2; q++) {                  \
            int kg = (k0) + akq + q * 4;                                 \
            int idx = sIdx[kg >> 8][ar];                                 \
            cpa16(A_ADDR(st, ar, akq + q * 4),                           \
                  nsb + (size_t)idx * Dd + (kg & (Dd - 1)));             \
        }                                                                \
        _Pragma("unroll") for (int q = 0; q < 2; q++)                    \
            cpa16(B_ADDR(st, bkr, bnq + q * 4),                          \
                  g_We1r + (size_t)((k0) + bkr) * Hh + colBase + bnq + q * 4); \
    }

    PIPELINE(32, LOAD_E1);

#pragma unroll
    for (int mt = 0; mt < 4; mt++) {
        int r0 = rowBase + wM + mt * 16 + grp;
#pragma unroll
        for (int nt = 0; nt < 4; nt++) {
            int c0 = colBase + wN + nt * 8 + tig * 2;
            float b0 = be1[c0], b1 = be1[c0 + 1];
            float* a = acc[mt][nt];
            *(float2*)(g_h + (size_t)r0 * Hh + c0) =
                make_float2(rndf(fmaxf(a[0] + b0, 0.f)), rndf(fmaxf(a[1] + b1, 0.f)));
            *(float2*)(g_h + (size_t)(r0 + 8) * Hh + c0) =
                make_float2(rndf(fmaxf(a[2] + b0, 0.f)), rndf(fmaxf(a[3] + b1, 0.f)));
        }
    }
}

// ---------------------------------------------------------------------------
// Edge MLP layer 2 + scatter: msgs = g_h @ We2r + b_e2; atomic add into g_inc
// M = 131072, N = 256, K = 512
__global__ __launch_bounds__(256, 2)
void k_edge2(const float* __restrict__ be2, const int* __restrict__ esnk)
{
    SMEM_TILES;
    __shared__ int sSnk[128];

    GEMM_PROLOG;

    const int rowBase = blockIdx.y * 128;
    const int colBase = blockIdx.x * 128;
    const int b  = rowBase >> 14;
    const int e0 = rowBase & (Ee - 1);

    if (tid < 128) sSnk[tid] = esnk[e0 + tid];
    __syncthreads();

    const float* Ag = g_h + (size_t)rowBase * Hh;

#define LOAD_E2(st, k0)                                                  \
    {                                                                    \
        _Pragma("unroll") for (int q = 0; q < 2; q++)                    \
            cpa16(A_ADDR(st, ar, akq + q * 4),                           \
                  Ag + (size_t)ar * Hh + (k0) + akq + q * 4);            \
        _Pragma("unroll") for (int q = 0; q < 2; q++)                    \
            cpa16(B_ADDR(st, bkr, bnq + q * 4),                          \
                  g_We2r + (size_t)((k0) + bkr) * MSGm + colBase + bnq + q * 4); \
    }

    PIPELINE(32, LOAD_E2);

    float* incb = g_inc + (size_t)b * Nn * MSGm;
#pragma unroll
    for (int mt = 0; mt < 4; mt++) {
        int r0 = wM + mt * 16 + grp;
        int s0 = sSnk[r0], s1 = sSnk[r0 + 8];
#pragma unroll
        for (int nt = 0; nt < 4; nt++) {
            int c0 = colBase + wN + nt * 8 + tig * 2;
            float b0 = be2[c0], b1 = be2[c0 + 1];
            float* a = acc[mt][nt];
            float* p0 = incb + (size_t)s0 * MSGm + c0;
            float* p1 = incb + (size_t)s1 * MSGm + c0;
            atomicAdd(p0,     a[0] + b0);
            atomicAdd(p0 + 1, a[1] + b1);
            atomicAdd(p1,     a[2] + b0);
            atomicAdd(p1 + 1, a[3] + b1);
        }
    }
}

// ---------------------------------------------------------------------------
// Node MLP layer 1: g_h2 = rna(relu(concat(g_inc, g_nsr) @ Wn1r + b_n1))
// M = 32768, N = 512, K = 512
__global__ __launch_bounds__(256, 2)
void k_node1(const float* __restrict__ bn1)
{
    SMEM_TILES;

    GEMM_PROLOG;

    const int rowBase = blockIdx.y * 128;
    const int colBase = blockIdx.x * 128;

#define LOAD_N1(st, k0)                                                  \
    {                                                                    \
        _Pragma("unroll") for (int q = 0; q < 2; q++) {                  \
            int kg = (k0) + akq + q * 4;                                 \
            const float* src = (kg < MSGm)                               \
                ? (g_inc + (size_t)(rowBase + ar) * MSGm + kg)           \
                : (g_nsr + (size_t)(rowBase + ar) * Dd + (kg - MSGm));   \
            cpa16(A_ADDR(st, ar, akq + q * 4), src);                     \
        }                                                                \
        _Pragma("unroll") for (int q = 0; q < 2; q++)                    \
            cpa16(B_ADDR(st, bkr, bnq + q * 4),                          \
                  g_Wn1r + (size_t)((k0) + bkr) * Hh + colBase + bnq + q * 4); \
    }

    PIPELINE(32, LOAD_N1);

#pragma unroll
    for (int mt = 0; mt < 4; mt++) {
        int r0 = rowBase + wM + mt * 16 + grp;
#pragma unroll
        for (int nt = 0; nt < 4; nt++) {
            int c0 = colBase + wN + nt * 8 + tig * 2;
            float b0 = bn1[c0], b1 = bn1[c0 + 1];
            float* a = acc[mt][nt];
            *(float2*)(g_h2 + (size_t)r0 * Hh + c0) =
                make_float2(rndf(fmaxf(a[0] + b0, 0.f)), rndf(fmaxf(a[1] + b1, 0.f)));
            *(float2*)(g_h2 + (size_t)(r0 + 8) * Hh + c0) =
                make_float2(rndf(fmaxf(a[2] + b0, 0.f)), rndf(fmaxf(a[3] + b1, 0.f)));
        }
    }
}

// ---------------------------------------------------------------------------
// Node MLP layer 2 + in-place update:
// upd = g_h2 @ Wn2r + b_n2; g_ns[:, 2+c] += upd; g_nsr[:, 2+c] = rna(g_ns)
// M = 32768, N = 254 (padded 256), K = 512
__global__ __launch_bounds__(256, 2)
void k_node2(const float* __restrict__ bn2)
{
    SMEM_TILES;

    GEMM_PROLOG;

    const int rowBase = blockIdx.y * 128;
    const int colBase = blockIdx.x * 128;

    const float* Ag = g_h2 + (size_t)rowBase * Hh;

#define LOAD_N2(st, k0)                                                  \
    {                                                                    \
        _Pragma("unroll") for (int q = 0; q < 2; q++)                    \
            cpa16(A_ADDR(st, ar, akq + q * 4),                           \
                  Ag + (size_t)ar * Hh + (k0) + akq + q * 4);            \
        _Pragma("unroll") for (int q = 0; q < 2; q++)                    \
            cpa16(B_ADDR(st, bkr, bnq + q * 4),                          \
                  g_Wn2r + (size_t)((k0) + bkr) * 256 + colBase + bnq + q * 4); \
    }

    PIPELINE(32, LOAD_N2);

#pragma unroll
    for (int mt = 0; mt < 4; mt++) {
        int r0 = rowBase + wM + mt * 16 + grp;
#pragma unroll
        for (int nt = 0; nt < 4; nt++) {
            int c0 = colBase + wN + nt * 8 + tig * 2;
            float* a = acc[mt][nt];
#pragma unroll
            for (int h = 0; h < 2; h++) {
                int c = c0 + h;
                if (c < UPDu) {
                    float bb = bn2[c];
                    size_t i0 = (size_t)r0 * Dd + 2 + c;
                    size_t i1 = (size_t)(r0 + 8) * Dd + 2 + c;
                    float v0 = g_ns[i0] + a[h]     + bb;
                    float v1 = g_ns[i1] + a[2 + h] + bb;
                    g_ns[i0] = v0;  g_nsr[i0] = rndf(v0);
                    g_ns[i1] = v1;  g_nsr[i1] = rndf(v1);
                }
            }
        }
    }
}

// ---------------------------------------------------------------------------
// Extraction: out[b,p,d] = sum_n attn[b,p,n] * ns[b,n,d]  (full precision)
__global__ __launch_bounds__(256)
void k_extract(const float* __restrict__ attn, float* __restrict__ out)
{
    const int p = blockIdx.x;
    const int b = blockIdx.y;
    const int d = threadIdx.x;

    const float* ap  = attn + ((size_t)b * Pp + p) * Nn;
    const float* nsb = g_ns + (size_t)b * Nn * Dd;

    __shared__ float sa[256];
    float acc0 = 0.f, acc1 = 0.f;
    for (int n0 = 0; n0 < Nn; n0 += 256) {
        __syncthreads();
        sa[d] = ap[n0 + d];
        __syncthreads();
#pragma unroll 8
        for (int n = 0; n < 256; n += 2) {
            acc0 = fmaf(sa[n],     nsb[(size_t)(n0 + n) * Dd + d],     acc0);
            acc1 = fmaf(sa[n + 1], nsb[(size_t)(n0 + n + 1) * Dd + d], acc1);
        }
    }
    out[((size_t)b * Pp + p) * Dd + d] = acc0 + acc1;
}

// ---------------------------------------------------------------------------
extern "C" void kernel_launch(void* const* d_in, const int* in_sizes, int n_in,
                              void* d_out, int out_size)
{
    const float* nodes = (const float*)d_in[0];
    const float* attn  = (const float*)d_in[1];
    const float* We1   = (const float*)d_in[2];
    const float* be1   = (const float*)d_in[3];
    const float* We2   = (const float*)d_in[4];
    const float* be2   = (const float*)d_in[5];
    const float* Wn1   = (const float*)d_in[6];
    const float* bn1   = (const float*)d_in[7];
    const float* Wn2   = (const float*)d_in[8];
    const float* bn2   = (const float*)d_in[9];
    const int*   esrc  = (const int*)d_in[10];
    const int*   esnk  = (const int*)d_in[11];
    float* out = (float*)d_out;

    float* dWe1r; cudaGetSymbolAddress((void**)&dWe1r, g_We1r);
    float* dWe2r; cudaGetSymbolAddress((void**)&dWe2r, g_We2r);
    float* dWn1r; cudaGetSymbolAddress((void**)&dWn1r, g_Wn1r);

    // Prologue: tf32-round weights + init state copies
    k_round<<<(2 * Dd * Hh + 255) / 256, 256>>>(We1, dWe1r, 2 * Dd * Hh);
    k_round<<<(Hh * MSGm + 255) / 256, 256>>>(We2, dWe2r, Hh * MSGm);
    k_round<<<((Dd + MSGm) * Hh + 255) / 256, 256>>>(Wn1, dWn1r, (Dd + MSGm) * Hh);
    k_round_pad_wn2<<<(Hh * 256 + 255) / 256, 256>>>(Wn2);
    k_copy_ns<<<(Bb * Nn * Dd + 255) / 256, 256>>>(nodes);

    for (int s = 0; s < STEPS; s++) {
        k_zero_inc<<<8192, 256>>>();
        k_edge1<<<dim3(Hh / 128,  (Bb * Ee) / 128), 256>>>(be1, esrc, esnk);
        k_edge2<<<dim3(MSGm / 128, (Bb * Ee) / 128), 256>>>(be2, esnk);
        k_round_inc<<<(Bb * Nn * MSGm + 255) / 256, 256>>>();
        k_node1<<<dim3(Hh / 128,  (Bb * Nn) / 128), 256>>>(bn1);
        k_node2<<<dim3(2,         (Bb * Nn) / 128), 256>>>(bn2);
    }

    k_extract<<<dim3(Pp, Bb), 256>>>(attn, out);
}

// round 11
// speedup vs baseline: 3.4725x; 1.3485x over previous
#include <cuda_runtime.h>
#include <cstdint>

// Problem constants (fixed by setup_inputs)
#define Bb   8
#define Nn   4096
#define Ee   16384
#define Pp   64
#define Dd   256
#define Hh   512
#define MSGm 256
#define UPDu 254
#define STEPS 3

#define SKA  20    // A smem row stride (words)
#define SKB  136   // B smem row stride (words)

// Scratch (device globals per harness allocation rules)
__device__ __align__(128) float g_ns  [(size_t)Bb * Nn * Dd];    // exact state
__device__ __align__(128) float g_nsr [(size_t)Bb * Nn * Dd];    // tf32-rounded state
__device__ __align__(128) float g_p   [(size_t)Bb * Nn * 1024];  // P = nsr @ [We1_top|We1_bot]
__device__ __align__(128) float g_inc [(size_t)Bb * Nn * MSGm];  // messages
__device__ __align__(128) float g_h2  [(size_t)Bb * Nn * Hh];    // rounded node hidden
__device__ __align__(128) float g_We1c[(size_t)Dd * 1024];       // combined+rounded W_e1
__device__ __align__(128) float g_We2r[(size_t)Hh * MSGm];
__device__ __align__(128) float g_Wn1r[(size_t)(Dd+MSGm) * Hh];
__device__ __align__(128) float g_Wn2r[(size_t)Hh * 256];        // padded 254 -> 256

// ---------------------------------------------------------------------------
__device__ __forceinline__ uint32_t f2tf(float x) {
    uint32_t u;
    asm("cvt.rna.tf32.f32 %0, %1;" : "=r"(u) : "f"(x));
    return u;
}
__device__ __forceinline__ float rndf(float x) { return __uint_as_float(f2tf(x)); }

__device__ __forceinline__ void mma8(float* c, uint32_t a0, uint32_t a1,
                                     uint32_t a2, uint32_t a3,
                                     uint32_t b0, uint32_t b1) {
    asm volatile(
        "mma.sync.aligned.m16n8k8.row.col.f32.tf32.tf32.f32 "
        "{%0,%1,%2,%3}, {%4,%5,%6,%7}, {%8,%9}, {%0,%1,%2,%3};"
        : "+f"(c[0]), "+f"(c[1]), "+f"(c[2]), "+f"(c[3])
        : "r"(a0), "r"(a1), "r"(a2), "r"(a3), "r"(b0), "r"(b1));
}

__device__ __forceinline__ void ldsm4(uint32_t& r0, uint32_t& r1,
                                      uint32_t& r2, uint32_t& r3, uint32_t addr) {
    asm volatile("ldmatrix.sync.aligned.m8n8.x4.shared.b16 {%0,%1,%2,%3}, [%4];"
                 : "=r"(r0), "=r"(r1), "=r"(r2), "=r"(r3) : "r"(addr));
}

__device__ __forceinline__ void cpa16(uint32_t dst, const float* src) {
    asm volatile("cp.async.ca.shared.global [%0], [%1], 16;"
                 :: "r"(dst), "l"(src));
}
#define CP_COMMIT asm volatile("cp.async.commit_group;")
#define CP_WAIT1  asm volatile("cp.async.wait_group 1;")
#define CP_WAIT0  asm volatile("cp.async.wait_group 0;")

// ---------------------------------------------------------------------------
// Prologue / utility kernels
__global__ void k_round(const float* __restrict__ src, float* __restrict__ dst, int n) {
    int i = blockIdx.x * blockDim.x + threadIdx.x;
    if (i < n) dst[i] = rndf(src[i]);
}

__global__ void k_make_we1c(const float* __restrict__ We1) {
    int i = blockIdx.x * blockDim.x + threadIdx.x;   // over Dd*1024
    if (i < Dd * 1024) {
        int k = i >> 10, j = i & 1023;
        float v = (j < Hh) ? We1[k * Hh + j] : We1[(Dd + k) * Hh + (j - Hh)];
        g_We1c[i] = rndf(v);
    }
}

__global__ void k_round_pad_wn2(const float* __restrict__ src) {
    int i = blockIdx.x * blockDim.x + threadIdx.x;   // over Hh*256
    if (i < Hh * 256) {
        int r = i >> 8, c = i & 255;
        g_Wn2r[i] = (c < UPDu) ? rndf(src[r * UPDu + c]) : 0.f;
    }
}

__global__ void k_copy_ns(const float* __restrict__ src) {
    size_t i = (size_t)blockIdx.x * blockDim.x + threadIdx.x;
    if (i < (size_t)Bb * Nn * Dd) {
        float v = src[i];
        g_ns[i]  = v;
        g_nsr[i] = rndf(v);
    }
}

__global__ void k_zero_inc() {
    size_t i = (size_t)blockIdx.x * blockDim.x + threadIdx.x;
    if (i < ((size_t)Bb * Nn * MSGm) / 4)
        ((float4*)g_inc)[i] = make_float4(0.f, 0.f, 0.f, 0.f);
}

__global__ void k_round_inc() {
    size_t i = (size_t)blockIdx.x * blockDim.x + threadIdx.x;
    if (i < (size_t)Bb * Nn * MSGm) g_inc[i] = rndf(g_inc[i]);
}

// ---------------------------------------------------------------------------
// 256 threads = 8 warps; block tile 128(M) x 128(N), K-step 16, 2-stage cp.async.
// Warp tile 64x32 = 4x4 m16n8k8 mmas.

#define GEMM_PROLOG                                                      \
    const int tid  = threadIdx.x;                                        \
    const int lane = tid & 31;                                           \
    const int warp = tid >> 5;                                           \
    const int grp  = lane >> 2;                                          \
    const int tig  = lane & 3;                                           \
    const int wM   = (warp & 1) * 64;                                    \
    const int wN   = (warp >> 1) * 32;                                   \
    const int ar   = tid >> 1;            /* A row 0..127 */             \
    const int akq  = (tid & 1) * 8;       /* A k chunk 0/8 */            \
    const int bkr  = tid >> 4;            /* B k row 0..15 */            \
    const int bnq  = (tid & 15) * 8;      /* B n chunk */                \
    const int lrow = lane & 15;           /* LDSM row-in-tile */         \
    const int lcol = (lane >> 4) * 4;     /* LDSM col offset */          \
    const uint32_t sA = (uint32_t)__cvta_generic_to_shared(&As[0][0][0]);\
    const uint32_t sB = (uint32_t)__cvta_generic_to_shared(&Bs[0][0][0]);\
    float acc[4][4][4];                                                  \
    _Pragma("unroll") for (int i = 0; i < 4; i++)                        \
    _Pragma("unroll") for (int j = 0; j < 4; j++)                        \
    _Pragma("unroll") for (int q = 0; q < 4; q++) acc[i][j][q] = 0.f;

#define A_ADDR(st, m, k) (sA + (((st) * 128 + (m)) * SKA + (k)) * 4u)
#define B_ADDR(st, k, n) (sB + (((st) * 16  + (k)) * SKB + (n)) * 4u)

#define COMPUTE(st)                                                      \
    _Pragma("unroll") for (int kb = 0; kb < 16; kb += 8) {               \
        uint32_t af[4][4], bf[4][2];                                     \
        _Pragma("unroll") for (int mt = 0; mt < 4; mt++)                 \
            ldsm4(af[mt][0], af[mt][1], af[mt][2], af[mt][3],            \
                  A_ADDR(st, wM + mt * 16 + lrow, kb + lcol));           \
        _Pragma("unroll") for (int nt = 0; nt < 4; nt++) {               \
            int cc = wN + nt * 8 + grp;                                  \
            bf[nt][0] = Bs[st][kb + tig][cc];                            \
            bf[nt][1] = Bs[st][kb + tig + 4][cc];                        \
        }                                                                \
        _Pragma("unroll") for (int mt = 0; mt < 4; mt++)                 \
        _Pragma("unroll") for (int nt = 0; nt < 4; nt++)                 \
            mma8(acc[mt][nt], af[mt][0], af[mt][1], af[mt][2],           \
                 af[mt][3], bf[nt][0], bf[nt][1]);                       \
    }

#define PIPELINE(NITER, LOADER)                                          \
    LOADER(0, 0);                                                        \
    CP_COMMIT;                                                           \
    for (int it = 0; it < (NITER); it++) {                               \
        if (it + 1 < (NITER)) {                                          \
            LOADER((it + 1) & 1, (it + 1) * 16);                         \
            CP_COMMIT;                                                   \
            CP_WAIT1;                                                    \
        } else {                                                         \
            CP_WAIT0;                                                    \
        }                                                                \
        __syncthreads();                                                 \
        COMPUTE(it & 1);                                                 \
        __syncthreads();                                                 \
    }

#define SMEM_TILES                                                       \
    __shared__ uint32_t As[2][128][SKA];                                 \
    __shared__ uint32_t Bs[2][16][SKB];

// ---------------------------------------------------------------------------
// Node-projection GEMM: g_p = g_nsr @ g_We1c   (no bias, no relu, raw fp32 out)
// M = B*N = 32768, N = 1024, K = 256
__global__ __launch_bounds__(256, 2)
void k_pre()
{
    SMEM_TILES;
    GEMM_PROLOG;

    const int rowBase = blockIdx.y * 128;
    const int colBase = blockIdx.x * 128;

#define LOAD_P(st, k0)                                                   \
    {                                                                    \
        _Pragma("unroll") for (int q = 0; q < 2; q++)                    \
            cpa16(A_ADDR(st, ar, akq + q * 4),                           \
                  g_nsr + (size_t)(rowBase + ar) * Dd + (k0) + akq + q * 4); \
        _Pragma("unroll") for (int q = 0; q < 2; q++)                    \
            cpa16(B_ADDR(st, bkr, bnq + q * 4),                          \
                  g_We1c + (size_t)((k0) + bkr) * 1024 + colBase + bnq + q * 4); \
    }

    PIPELINE(16, LOAD_P);

#pragma unroll
    for (int mt = 0; mt < 4; mt++) {
        int r0 = rowBase + wM + mt * 16 + grp;
#pragma unroll
        for (int nt = 0; nt < 4; nt++) {
            int c0 = colBase + wN + nt * 8 + tig * 2;
            float* a = acc[mt][nt];
            *(float2*)(g_p + (size_t)r0 * 1024 + c0)       = make_float2(a[0], a[1]);
            *(float2*)(g_p + (size_t)(r0 + 8) * 1024 + c0) = make_float2(a[2], a[3]);
        }
    }
}

// ---------------------------------------------------------------------------
// Fused edge MLP + scatter:
//   h[e,k]  = rna(relu(P[src[e]][k] + P[snk[e]][512+k] + be1[k]))  (built in smem)
//   msgs    = h @ We2r + be2 ;  atomicAdd into g_inc[snk]
// M = B*E = 131072, N = 256, K = 512
__global__ __launch_bounds__(256, 2)
void k_edge2f(const float* __restrict__ be1, const float* __restrict__ be2,
              const int* __restrict__ esrc, const int* __restrict__ esnk)
{
    SMEM_TILES;
    __shared__ int sIdx[2][128];

    GEMM_PROLOG;

    const int rowBase = blockIdx.y * 128;
    const int colBase = blockIdx.x * 128;
    const int b  = rowBase >> 14;
    const int e0 = rowBase & (Ee - 1);

    if (tid < 128)      sIdx[0][tid]       = esrc[e0 + tid];
    else                sIdx[1][tid - 128] = esnk[e0 + tid - 128];
    __syncthreads();

    const float* Pb = g_p + (size_t)b * Nn * 1024;
    const size_t srcRow = (size_t)sIdx[0][ar] * 1024;
    const size_t snkRow = (size_t)sIdx[1][ar] * 1024 + 512;

    float4 u0, u1, v0, v1;   // A prefetch registers

    // ISSUE: gather LDGs for stage; COMMIT: combine+relu+rna+STS
#define ISSUE_EF(k0)                                                     \
    {                                                                    \
        u0 = *(const float4*)(Pb + srcRow + (k0) + akq);                 \
        u1 = *(const float4*)(Pb + srcRow + (k0) + akq + 4);             \
        v0 = *(const float4*)(Pb + snkRow + (k0) + akq);                 \
        v1 = *(const float4*)(Pb + snkRow + (k0) + akq + 4);             \
    }

#define COMMIT_EF(st, k0)                                                \
    {                                                                    \
        float4 b0 = *(const float4*)(be1 + (k0) + akq);                  \
        float4 b1 = *(const float4*)(be1 + (k0) + akq + 4);              \
        uint32_t* dst = (uint32_t*)&As[st][ar][akq];                     \
        dst[0] = f2tf(fmaxf(u0.x + v0.x + b0.x, 0.f));                   \
        dst[1] = f2tf(fmaxf(u0.y + v0.y + b0.y, 0.f));                   \
        dst[2] = f2tf(fmaxf(u0.z + v0.z + b0.z, 0.f));                   \
        dst[3] = f2tf(fmaxf(u0.w + v0.w + b0.w, 0.f));                   \
        dst[4] = f2tf(fmaxf(u1.x + v1.x + b1.x, 0.f));                   \
        dst[5] = f2tf(fmaxf(u1.y + v1.y + b1.y, 0.f));                   \
        dst[6] = f2tf(fmaxf(u1.z + v1.z + b1.z, 0.f));                   \
        dst[7] = f2tf(fmaxf(u1.w + v1.w + b1.w, 0.f));                   \
    }

#define LOADB_EF(st, k0)                                                 \
    _Pragma("unroll") for (int q = 0; q < 2; q++)                        \
        cpa16(B_ADDR(st, bkr, bnq + q * 4),                              \
              g_We2r + (size_t)((k0) + bkr) * MSGm + colBase + bnq + q * 4);

    // Stage 0
    ISSUE_EF(0);
    LOADB_EF(0, 0);
    CP_COMMIT;
    COMMIT_EF(0, 0);

    for (int it = 0; it < 32; it++) {
        if (it + 1 < 32) {
            ISSUE_EF((it + 1) * 16);
            LOADB_EF((it + 1) & 1, (it + 1) * 16);
            CP_COMMIT;
            CP_WAIT1;
        } else {
            CP_WAIT0;
        }
        __syncthreads();
        COMPUTE(it & 1);
        if (it + 1 < 32) COMMIT_EF((it + 1) & 1, (it + 1) * 16);
        __syncthreads();
    }

    float* incb = g_inc + (size_t)b * Nn * MSGm;
#pragma unroll
    for (int mt = 0; mt < 4; mt++) {
        int r0 = wM + mt * 16 + grp;
        int s0 = sIdx[1][r0], s1 = sIdx[1][r0 + 8];
#pragma unroll
        for (int nt = 0; nt < 4; nt++) {
            int c0 = colBase + wN + nt * 8 + tig * 2;
            float b0 = be2[c0], b1 = be2[c0 + 1];
            float* a = acc[mt][nt];
            float* p0 = incb + (size_t)s0 * MSGm + c0;
            float* p1 = incb + (size_t)s1 * MSGm + c0;
            atomicAdd(p0,     a[0] + b0);
            atomicAdd(p0 + 1, a[1] + b1);
            atomicAdd(p1,     a[2] + b0);
            atomicAdd(p1 + 1, a[3] + b1);
        }
    }
}

// ---------------------------------------------------------------------------
// Node MLP layer 1: g_h2 = rna(relu(concat(g_inc, g_nsr) @ Wn1r + b_n1))
// M = 32768, N = 512, K = 512
__global__ __launch_bounds__(256, 2)
void k_node1(const float* __restrict__ bn1)
{
    SMEM_TILES;
    GEMM_PROLOG;

    const int rowBase = blockIdx.y * 128;
    const int colBase = blockIdx.x * 128;

#define LOAD_N1(st, k0)                                                  \
    {                                                                    \
        _Pragma("unroll") for (int q = 0; q < 2; q++) {                  \
            int kg = (k0) + akq + q * 4;                                 \
            const float* src = (kg < MSGm)                               \
                ? (g_inc + (size_t)(rowBase + ar) * MSGm + kg)           \
                : (g_nsr + (size_t)(rowBase + ar) * Dd + (kg - MSGm));   \
            cpa16(A_ADDR(st, ar, akq + q * 4), src);                     \
        }                                                                \
        _Pragma("unroll") for (int q = 0; q < 2; q++)                    \
            cpa16(B_ADDR(st, bkr, bnq + q * 4),                          \
                  g_Wn1r + (size_t)((k0) + bkr) * Hh + colBase + bnq + q * 4); \
    }

    PIPELINE(32, LOAD_N1);

#pragma unroll
    for (int mt = 0; mt < 4; mt++) {
        int r0 = rowBase + wM + mt * 16 + grp;
#pragma unroll
        for (int nt = 0; nt < 4; nt++) {
            int c0 = colBase + wN + nt * 8 + tig * 2;
            float b0 = bn1[c0], b1 = bn1[c0 + 1];
            float* a = acc[mt][nt];
            *(float2*)(g_h2 + (size_t)r0 * Hh + c0) =
                make_float2(rndf(fmaxf(a[0] + b0, 0.f)), rndf(fmaxf(a[1] + b1, 0.f)));
            *(float2*)(g_h2 + (size_t)(r0 + 8) * Hh + c0) =
                make_float2(rndf(fmaxf(a[2] + b0, 0.f)), rndf(fmaxf(a[3] + b1, 0.f)));
        }
    }
}

// ---------------------------------------------------------------------------
// Node MLP layer 2 + in-place update
// M = 32768, N = 254 (padded 256), K = 512
__global__ __launch_bounds__(256, 2)
void k_node2(const float* __restrict__ bn2)
{
    SMEM_TILES;
    GEMM_PROLOG;

    const int rowBase = blockIdx.y * 128;
    const int colBase = blockIdx.x * 128;

    const float* Ag = g_h2 + (size_t)rowBase * Hh;

#define LOAD_N2(st, k0)                                                  \
    {                                                                    \
        _Pragma("unroll") for (int q = 0; q < 2; q++)                    \
            cpa16(A_ADDR(st, ar, akq + q * 4),                           \
                  Ag + (size_t)ar * Hh + (k0) + akq + q * 4);            \
        _Pragma("unroll") for (int q = 0; q < 2; q++)                    \
            cpa16(B_ADDR(st, bkr, bnq + q * 4),                          \
                  g_Wn2r + (size_t)((k0) + bkr) * 256 + colBase + bnq + q * 4); \
    }

    PIPELINE(32, LOAD_N2);

#pragma unroll
    for (int mt = 0; mt < 4; mt++) {
        int r0 = rowBase + wM + mt * 16 + grp;
#pragma unroll
        for (int nt = 0; nt < 4; nt++) {
            int c0 = colBase + wN + nt * 8 + tig * 2;
            float* a = acc[mt][nt];
#pragma unroll
            for (int h = 0; h < 2; h++) {
                int c = c0 + h;
                if (c < UPDu) {
                    float bb = bn2[c];
                    size_t i0 = (size_t)r0 * Dd + 2 + c;
                    size_t i1 = (size_t)(r0 + 8) * Dd + 2 + c;
                    float v0 = g_ns[i0] + a[h]     + bb;
                    float v1 = g_ns[i1] + a[2 + h] + bb;
                    g_ns[i0] = v0;  g_nsr[i0] = rndf(v0);
                    g_ns[i1] = v1;  g_nsr[i1] = rndf(v1);
                }
            }
        }
    }
}

// ---------------------------------------------------------------------------
// Extraction: out[b,p,d] = sum_n attn[b,p,n] * ns[b,n,d]  (full precision)
__global__ __launch_bounds__(256)
void k_extract(const float* __restrict__ attn, float* __restrict__ out)
{
    const int p = blockIdx.x;
    const int b = blockIdx.y;
    const int d = threadIdx.x;

    const float* ap  = attn + ((size_t)b * Pp + p) * Nn;
    const float* nsb = g_ns + (size_t)b * Nn * Dd;

    __shared__ float sa[256];
    float acc0 = 0.f, acc1 = 0.f;
    for (int n0 = 0; n0 < Nn; n0 += 256) {
        __syncthreads();
        sa[d] = ap[n0 + d];
        __syncthreads();
#pragma unroll 8
        for (int n = 0; n < 256; n += 2) {
            acc0 = fmaf(sa[n],     nsb[(size_t)(n0 + n) * Dd + d],     acc0);
            acc1 = fmaf(sa[n + 1], nsb[(size_t)(n0 + n + 1) * Dd + d], acc1);
        }
    }
    out[((size_t)b * Pp + p) * Dd + d] = acc0 + acc1;
}

// ---------------------------------------------------------------------------
extern "C" void kernel_launch(void* const* d_in, const int* in_sizes, int n_in,
                              void* d_out, int out_size)
{
    const float* nodes = (const float*)d_in[0];
    const float* attn  = (const float*)d_in[1];
    const float* We1   = (const float*)d_in[2];
    const float* be1   = (const float*)d_in[3];
    const float* We2   = (const float*)d_in[4];
    const float* be2   = (const float*)d_in[5];
    const float* Wn1   = (const float*)d_in[6];
    const float* bn1   = (const float*)d_in[7];
    const float* Wn2   = (const float*)d_in[8];
    const float* bn2   = (const float*)d_in[9];
    const int*   esrc  = (const int*)d_in[10];
    const int*   esnk  = (const int*)d_in[11];
    float* out = (float*)d_out;

    float* dWe2r; cudaGetSymbolAddress((void**)&dWe2r, g_We2r);
    float* dWn1r; cudaGetSymbolAddress((void**)&dWn1r, g_Wn1r);

    // Prologue: combined/rounded weights + state copies
    k_make_we1c<<<(Dd * 1024 + 255) / 256, 256>>>(We1);
    k_round<<<(Hh * MSGm + 255) / 256, 256>>>(We2, dWe2r, Hh * MSGm);
    k_round<<<((Dd + MSGm) * Hh + 255) / 256, 256>>>(Wn1, dWn1r, (Dd + MSGm) * Hh);
    k_round_pad_wn2<<<(Hh * 256 + 255) / 256, 256>>>(Wn2);
    k_copy_ns<<<(Bb * Nn * Dd + 255) / 256, 256>>>(nodes);

    for (int s = 0; s < STEPS; s++) {
        k_zero_inc<<<8192, 256>>>();
        k_pre<<<dim3(1024 / 128, (Bb * Nn) / 128), 256>>>();
        k_edge2f<<<dim3(MSGm / 128, (Bb * Ee) / 128), 256>>>(be1, be2, esrc, esnk);
        k_round_inc<<<(Bb * Nn * MSGm + 255) / 256, 256>>>();
        k_node1<<<dim3(Hh / 128, (Bb * Nn) / 128), 256>>>(bn1);
        k_node2<<<dim3(2, (Bb * Nn) / 128), 256>>>(bn2);
    }

    k_extract<<<dim3(Pp, Bb), 256>>>(attn, out);
}